// round 9
// baseline (speedup 1.0000x reference)
#include <cuda_runtime.h>
#include <cuda_bf16.h>
#include <math.h>

// Problem constants (fixed by setup_inputs)
#define BS 2
#define NPT 1024
#define HH 8
#define DH 64
#define KNN 16
#define EMB 512
#define INNER 512
#define AINNER 256
#define POSH 64

// ---------------- packed f32x2 helpers (sm_103a) ----------------
__device__ __forceinline__ unsigned long long pk2(float lo, float hi) {
    unsigned long long r;
    asm("mov.b64 %0, {%1, %2};" : "=l"(r) : "f"(lo), "f"(hi));
    return r;
}
__device__ __forceinline__ float2 upk2(unsigned long long p) {
    float lo, hi;
    asm("mov.b64 {%0, %1}, %2;" : "=f"(lo), "=f"(hi) : "l"(p));
    return make_float2(lo, hi);
}
#define FMA2(acc, a, b) \
    asm("fma.rn.f32x2 %0, %1, %2, %0;" : "+l"(acc) : "l"(a), "l"(b))

// ---------------- scratch (device globals; no allocation allowed) ----------------
__device__ float g_q[BS*HH*NPT*DH];     // (b,h,i,d)
__device__ float g_k[BS*HH*NPT*DH];
__device__ float g_v[BS*HH*NPT*DH];
__device__ int   g_nbr[BS*NPT*KNN];     // (b,i,j)
__device__ float g_hid[BS*NPT*KNN*POSH];
__device__ float g_rpe[BS*NPT*KNN*INNER];   // (b,i,j,hd)
__device__ float g_vg[BS*HH*NPT*KNN*DH];    // (b,h,i,j,d)
__device__ float g_attn[BS*HH*NPT*KNN*DH];  // (b,h,i,j,d)
__device__ float g_part[16*8*1024];
__device__ float g_invn[BS*HH*KNN*DH];      // (b,h,j,d)
__device__ float g_agg[BS*NPT*INNER];       // (b,i,hd)

// ---------------- KNN: per (b,i) top-16 smallest d2, tie-break lower idx ----------------
__global__ void knn_kernel(const float* __restrict__ canon, int* __restrict__ nbr) {
    int bi = blockIdx.x;               // 0..2047
    int b = bi >> 10, i = bi & 1023;
    __shared__ float dist[NPT];
    __shared__ unsigned long long red[8];
    const float* cb = canon + b * NPT * 3;
    float x = cb[i*3+0], y = cb[i*3+1], z = cb[i*3+2];
    for (int p = threadIdx.x; p < NPT; p += 256) {
        float dx = cb[p*3+0]-x, dy = cb[p*3+1]-y, dz = cb[p*3+2]-z;
        dist[p] = dx*dx + dy*dy + dz*dz;
    }
    __syncthreads();
    for (int s = 0; s < KNN; s++) {
        unsigned long long best = ~0ULL;
        for (int p = threadIdx.x; p < NPT; p += 256) {
            unsigned long long key = (((unsigned long long)__float_as_uint(dist[p])) << 32) | (unsigned)p;
            best = (key < best) ? key : best;
        }
        #pragma unroll
        for (int o = 16; o > 0; o >>= 1) {
            unsigned long long other = __shfl_xor_sync(0xffffffffu, best, o);
            best = (other < best) ? other : best;
        }
        if ((threadIdx.x & 31) == 0) red[threadIdx.x >> 5] = best;
        __syncthreads();
        if (threadIdx.x == 0) {
            unsigned long long m = red[0];
            #pragma unroll
            for (int w = 1; w < 8; w++) m = (red[w] < m) ? red[w] : m;
            int p = (int)(m & 0xffffffffu);
            nbr[bi*KNN + s] = p;
            dist[p] = __int_as_float(0x7f800000);  // +inf
        }
        __syncthreads();
    }
}

// ---------------- fused QKV projection: one launch, gridDim.z selects matrix ----------------
// C layout: scatter to (b,h,i,d); A: 2048x512, B: 512x512
__global__ __launch_bounds__(256) void qkv_kernel(
    const float* __restrict__ A0, const float* __restrict__ A1, const float* __restrict__ A2,
    const float* __restrict__ B0, const float* __restrict__ B1, const float* __restrict__ B2,
    float* __restrict__ C0, float* __restrict__ C1, float* __restrict__ C2)
{
    const int z = blockIdx.z;
    const float* A = (z == 0) ? A0 : (z == 1) ? A1 : A2;
    const float* B = (z == 0) ? B0 : (z == 1) ? B1 : B2;
    float*       C = (z == 0) ? C0 : (z == 1) ? C1 : C2;
    const int Kd = EMB, N = INNER;

    __shared__ float As[16][68];
    __shared__ float Bs[16][64];
    const int t = threadIdx.x;
    const int m0 = blockIdx.y * 64, n0 = blockIdx.x * 64;
    const int tx = t & 15, ty = t >> 4;
    const int am = t >> 2, ak = (t & 3) * 4;
    const int bk = t >> 4, bn = (t & 15) * 4;
    unsigned long long acc[4][2];
    #pragma unroll
    for (int u = 0; u < 4; u++) { acc[u][0] = 0ULL; acc[u][1] = 0ULL; }

    for (int k0 = 0; k0 < Kd; k0 += 16) {
        float4 av = *(const float4*)(A + (size_t)(m0 + am) * Kd + k0 + ak);
        float4 bv = *(const float4*)(B + (size_t)(bk + k0) * N + n0 + bn);
        As[ak+0][am] = av.x; As[ak+1][am] = av.y; As[ak+2][am] = av.z; As[ak+3][am] = av.w;
        *(float4*)&Bs[bk][bn] = bv;
        __syncthreads();
        #pragma unroll
        for (int k = 0; k < 16; k++) {
            float4 a = *(const float4*)&As[k][ty*4];
            float4 bq = *(const float4*)&Bs[k][tx*4];
            unsigned long long bp0 = pk2(bq.x, bq.y);
            unsigned long long bp1 = pk2(bq.z, bq.w);
            float ar[4] = {a.x, a.y, a.z, a.w};
            #pragma unroll
            for (int u = 0; u < 4; u++) {
                unsigned long long ap = pk2(ar[u], ar[u]);
                FMA2(acc[u][0], ap, bp0);
                FMA2(acc[u][1], ap, bp1);
            }
        }
        __syncthreads();
    }

    // scatter to (b,h,i,d) layout: row r=(b,i), col c=(h,d)
    int h = n0 >> 6;
    int d0 = tx * 4;
    #pragma unroll
    for (int u = 0; u < 4; u++) {
        int r = m0 + ty*4 + u;
        int b_ = r >> 10, i = r & 1023;
        float2 c0 = upk2(acc[u][0]), c1 = upk2(acc[u][1]);
        float4 o = make_float4(c0.x, c0.y, c1.x, c1.y);
        *(float4*)(C + ((size_t)((b_*8 + h)*1024 + i))*64 + d0) = o;
    }
}

// ---------------- generic 64x64-tile fp32 GEMM (packed f32x2 inner), C=A@B+bias ----------------
__global__ __launch_bounds__(256) void gemm64(
    const float* __restrict__ A, const float* __restrict__ B,
    const float* __restrict__ bias, float* __restrict__ C,
    int M, int N, int Kd)
{
    __shared__ float As[16][68];
    __shared__ float Bs[16][64];
    const int t = threadIdx.x;
    const int m0 = blockIdx.y * 64, n0 = blockIdx.x * 64;
    const int tx = t & 15, ty = t >> 4;
    const int am = t >> 2, ak = (t & 3) * 4;
    const int bk = t >> 4, bn = (t & 15) * 4;
    unsigned long long acc[4][2];
    #pragma unroll
    for (int u = 0; u < 4; u++) { acc[u][0] = 0ULL; acc[u][1] = 0ULL; }

    for (int k0 = 0; k0 < Kd; k0 += 16) {
        float4 av = *(const float4*)(A + (size_t)(m0 + am) * Kd + k0 + ak);
        float4 bv = *(const float4*)(B + (size_t)(bk + k0) * N + n0 + bn);
        As[ak+0][am] = av.x; As[ak+1][am] = av.y; As[ak+2][am] = av.z; As[ak+3][am] = av.w;
        *(float4*)&Bs[bk][bn] = bv;
        __syncthreads();
        #pragma unroll
        for (int k = 0; k < 16; k++) {
            float4 a = *(const float4*)&As[k][ty*4];
            float4 bq = *(const float4*)&Bs[k][tx*4];
            unsigned long long bp0 = pk2(bq.x, bq.y);
            unsigned long long bp1 = pk2(bq.z, bq.w);
            float ar[4] = {a.x, a.y, a.z, a.w};
            #pragma unroll
            for (int u = 0; u < 4; u++) {
                unsigned long long ap = pk2(ar[u], ar[u]);
                FMA2(acc[u][0], ap, bp0);
                FMA2(acc[u][1], ap, bp1);
            }
        }
        __syncthreads();
    }

    float4 bb = *(const float4*)(bias + n0 + tx*4);
    #pragma unroll
    for (int u = 0; u < 4; u++) {
        int m = m0 + ty*4 + u;
        float2 c0 = upk2(acc[u][0]), c1 = upk2(acc[u][1]);
        float4 o = make_float4(c0.x+bb.x, c0.y+bb.y, c1.x+bb.z, c1.y+bb.w);
        *(float4*)(C + (size_t)m * N + n0 + tx*4) = o;
    }
}

// ---------------- rpe hidden: relu(rel @ pos_w1 + pos_b1), per (b,i,j) ----------------
__global__ void hid_kernel(const float* __restrict__ canon, const int* __restrict__ nbr,
                           const float* __restrict__ w1, const float* __restrict__ b1,
                           float* __restrict__ hid)
{
    int idx = blockIdx.x * blockDim.x + threadIdx.x;   // over 32768*64
    if (idx >= BS*NPT*KNN*POSH) return;
    int row = idx >> 6, u = idx & 63;
    int b = row >> 14;              // row = b*16384 + i*16 + j
    int i = (row >> 4) & 1023;
    int nv = nbr[row];
    const float* cb = canon + b * NPT * 3;
    float r0 = cb[nv*3+0] - cb[i*3+0];
    float r1 = cb[nv*3+1] - cb[i*3+1];
    float r2 = cb[nv*3+2] - cb[i*3+2];
    float s = fmaf(r0, w1[0*64+u], fmaf(r1, w1[1*64+u], fmaf(r2, w1[2*64+u], b1[u])));
    hid[(size_t)row*64 + u] = fmaxf(s, 0.f);
}

// ---------------- fused gather + attn MLP + softmax(j), 512 threads, f32x2 ----------------
// block = (i-tile of 16) x (h) x (b); 512 threads; 256 rows = 16 i x 16 j
// warp mapping: half = wid>>3 (row half), cg = wid&7 (8-col group)
//   rows: u*64 + half*32 + lane (u=0..3)  -> 0..255
//   cols: cg*8 + 2*vp + {0,1}   (vp=0..3) -> 0..63
#define SMEM_XT   (64*257)
#define SMEM_HT   (64*260)
#define SMEM_W    (64*66)
#define SMEM_MLP_BYTES ((SMEM_XT + SMEM_HT + 2*SMEM_W) * 4)

__global__ __launch_bounds__(512, 1) void mlp_kernel(
    const float* __restrict__ qbuf, const float* __restrict__ kbuf, const float* __restrict__ vbuf,
    const float* __restrict__ rpe, const int* __restrict__ nbr,
    const float* __restrict__ aw1, const float* __restrict__ ab1,
    const float* __restrict__ aw2, const float* __restrict__ ab2,
    float* __restrict__ vg, float* __restrict__ attn)
{
    extern __shared__ float sm[];
    float* XT  = sm;                       // [d][r] stride 257
    float* HT  = sm + SMEM_XT;             // [e][r] stride 260 (reused as SIM [r][d] stride 65)
    float* W1s = sm + SMEM_XT + SMEM_HT;   // [d][e'] stride 66 (even -> aligned LDS.64 pairs)
    float* W2s = W1s + SMEM_W;             // [e'][d] stride 66
    const int t = threadIdx.x;
    const int it = blockIdx.x, h = blockIdx.y, b = blockIdx.z;
    const int i0 = it * 16;
    const int bh = b * 8 + h;

    // Phase 0: scrambled gather, build X = qg-kg+rpe (transposed in smem), write vg = vgath+rpe
    for (int idx = t; idx < 256 * 64; idx += 512) {
        const int r = idx >> 6, d = idx & 63;
        const int ii = r >> 4, j = r & 15;
        const int i = i0 + ii;
        const int nv = nbr[(b*1024 + h*128 + (i >> 3))*16 + ((i & 7)*2) + (j >> 3)];
        const int hs = nv >> 7;
        const int isrc = ((nv & 127) << 3) | (j & 7);
        const size_t src = ((size_t)((b*8 + hs)*1024 + isrc))*64 + d;
        const float rp = rpe[((size_t)((b*1024 + i)*16 + j))*512 + h*64 + d];
        XT[d*257 + r] = qbuf[src] - kbuf[src] + rp;
        vg[((size_t)((bh*1024 + i)*16 + j))*64 + d] = vbuf[src] + rp;
    }

    const int lane = t & 31, wid = t >> 5;
    const int half = wid >> 3, cg = wid & 7;
    const int rbase = half*32 + lane;       // + u*64
    const int cbase = cg*8;                 // + 2*vp

    unsigned long long acc2[4][4];
    #pragma unroll
    for (int u = 0; u < 4; u++)
        #pragma unroll
        for (int vp = 0; vp < 4; vp++) acc2[u][vp] = 0ULL;

    for (int ec = 0; ec < 4; ec++) {
        __syncthreads();
        // stage weights for this e-chunk
        for (int idx = t; idx < 4096; idx += 512) {
            int e = idx >> 6, d = idx & 63;
            W1s[d*66 + e] = aw1[(size_t)(h*256 + ec*64 + e)*64 + d];
        }
        for (int idx = t; idx < 4096; idx += 512) {
            int d = idx >> 6, e = idx & 63;
            W2s[e*66 + d] = aw2[(size_t)(h*64 + d)*256 + ec*64 + e];
        }
        __syncthreads();

        // GEMM1: H[r][e'] = relu(sum_d X[r][d]*aw1[e][d] + ab1[e])
        unsigned long long acc1[4][4];
        #pragma unroll
        for (int u = 0; u < 4; u++)
            #pragma unroll
            for (int vp = 0; vp < 4; vp++) acc1[u][vp] = 0ULL;
        #pragma unroll 4
        for (int d = 0; d < 64; d++) {
            unsigned long long ap[4], wp[4];
            #pragma unroll
            for (int u = 0; u < 4; u++) {
                float a = XT[d*257 + u*64 + rbase];
                ap[u] = pk2(a, a);
            }
            #pragma unroll
            for (int vp = 0; vp < 4; vp++)
                wp[vp] = *(const unsigned long long*)&W1s[d*66 + cbase + 2*vp];
            #pragma unroll
            for (int u = 0; u < 4; u++)
                #pragma unroll
                for (int vp = 0; vp < 4; vp++)
                    FMA2(acc1[u][vp], ap[u], wp[vp]);
        }
        #pragma unroll
        for (int vp = 0; vp < 4; vp++) {
            float b0 = ab1[h*256 + ec*64 + cbase + 2*vp];
            float b1 = ab1[h*256 + ec*64 + cbase + 2*vp + 1];
            #pragma unroll
            for (int u = 0; u < 4; u++) {
                float2 c = upk2(acc1[u][vp]);
                HT[(cbase + 2*vp)*260 + u*64 + rbase]     = fmaxf(c.x + b0, 0.f);
                HT[(cbase + 2*vp + 1)*260 + u*64 + rbase] = fmaxf(c.y + b1, 0.f);
            }
        }
        __syncthreads();

        // GEMM2: SIM[r][d] += sum_e' H[r][e']*aw2[d][e]
        #pragma unroll 4
        for (int e = 0; e < 64; e++) {
            unsigned long long ap[4], wp[4];
            #pragma unroll
            for (int u = 0; u < 4; u++) {
                float a = HT[e*260 + u*64 + rbase];
                ap[u] = pk2(a, a);
            }
            #pragma unroll
            for (int vp = 0; vp < 4; vp++)
                wp[vp] = *(const unsigned long long*)&W2s[e*66 + cbase + 2*vp];
            #pragma unroll
            for (int u = 0; u < 4; u++)
                #pragma unroll
                for (int vp = 0; vp < 4; vp++)
                    FMA2(acc2[u][vp], ap[u], wp[vp]);
        }
    }
    __syncthreads();

    // store SIM (+ab2) into smem (reuse HT space), stride 65
    float* SIM = HT;
    #pragma unroll
    for (int vp = 0; vp < 4; vp++) {
        float b0 = ab2[h*64 + cbase + 2*vp];
        float b1 = ab2[h*64 + cbase + 2*vp + 1];
        #pragma unroll
        for (int u = 0; u < 4; u++) {
            float2 c = upk2(acc2[u][vp]);
            SIM[(u*64 + rbase)*65 + cbase + 2*vp]     = c.x + b0;
            SIM[(u*64 + rbase)*65 + cbase + 2*vp + 1] = c.y + b1;
        }
    }
    __syncthreads();

    // softmax over j for each (ii, d)
    for (int p = t; p < 16 * 64; p += 512) {
        int ii = p >> 6, d = p & 63;
        int i = i0 + ii;
        float s[16];
        float m = -1e30f;
        #pragma unroll
        for (int j = 0; j < 16; j++) { s[j] = SIM[(ii*16 + j)*65 + d]; m = fmaxf(m, s[j]); }
        float sum = 0.f;
        #pragma unroll
        for (int j = 0; j < 16; j++) { s[j] = __expf(s[j] - m); sum += s[j]; }
        float inv = 1.f / sum;
        #pragma unroll
        for (int j = 0; j < 16; j++)
            attn[((size_t)((bh*1024 + i)*16 + j))*64 + d] = s[j] * inv;
    }
}

// ---------------- norm over i: partial sums then finalize 1/max(sqrt,1e-12) ----------------
__global__ void norm_part_kernel(const float* __restrict__ attn, float* __restrict__ part) {
    int bh = blockIdx.x, s = blockIdx.y;   // 16 x 8
    const float* base = attn + (size_t)bh * 1024 * 1024;
    float acc[4] = {0.f, 0.f, 0.f, 0.f};
    for (int i = s*128; i < s*128 + 128; i++) {
        #pragma unroll
        for (int q = 0; q < 4; q++) {
            int jd = q*256 + threadIdx.x;
            float v = base[(size_t)i*1024 + jd];
            acc[q] = fmaf(v, v, acc[q]);
        }
    }
    #pragma unroll
    for (int q = 0; q < 4; q++)
        part[(size_t)(bh*8 + s)*1024 + q*256 + threadIdx.x] = acc[q];
}

__global__ void norm_final_kernel(const float* __restrict__ part, float* __restrict__ invn) {
    int bh = blockIdx.x;
    #pragma unroll
    for (int q = 0; q < 4; q++) {
        int jd = q*256 + threadIdx.x;
        float s = 0.f;
        #pragma unroll
        for (int seg = 0; seg < 8; seg++) s += part[(size_t)(bh*8 + seg)*1024 + jd];
        float n = sqrtf(s);
        invn[bh*1024 + jd] = 1.f / fmaxf(n, 1e-12f);
    }
}

// ---------------- aggregate: agg[b,i,h*64+d] = sum_j attn*inv_norm*vg ----------------
__global__ void agg_kernel(const float* __restrict__ attn, const float* __restrict__ vg,
                           const float* __restrict__ invn, float* __restrict__ aggb) {
    int ic = blockIdx.x, h = blockIdx.y, b = blockIdx.z;   // 256 x 8 x 2
    int bh = b*8 + h;
    __shared__ float inv_s[1024];
    for (int p = threadIdx.x; p < 1024; p += 256) inv_s[p] = invn[bh*1024 + p];
    __syncthreads();
    int ii = threadIdx.x >> 6, d = threadIdx.x & 63;
    int i = ic*4 + ii;
    const float* ab = attn + (size_t)(bh*1024 + i) * 1024;
    const float* vb = vg + (size_t)(bh*1024 + i) * 1024;
    float acc = 0.f;
    #pragma unroll
    for (int j = 0; j < 16; j++)
        acc = fmaf(ab[j*64 + d] * inv_s[j*64 + d], vb[j*64 + d], acc);
    aggb[(size_t)(b*1024 + i)*512 + h*64 + d] = acc;
}

// ---------------- host launcher ----------------
extern "C" void kernel_launch(void* const* d_in, const int* in_sizes, int n_in,
                              void* d_out, int out_size) {
    const float* query  = (const float*)d_in[0];
    const float* key_in = (const float*)d_in[1];
    const float* value  = (const float*)d_in[2];
    const float* canon  = (const float*)d_in[3];
    const float* w_q    = (const float*)d_in[4];
    const float* w_k    = (const float*)d_in[5];
    const float* w_v    = (const float*)d_in[6];
    const float* w_out  = (const float*)d_in[7];
    const float* b_out  = (const float*)d_in[8];
    const float* pos_w1 = (const float*)d_in[9];
    const float* pos_b1 = (const float*)d_in[10];
    const float* pos_w2 = (const float*)d_in[11];
    const float* pos_b2 = (const float*)d_in[12];
    const float* aw1    = (const float*)d_in[13];
    const float* ab1    = (const float*)d_in[14];
    const float* aw2    = (const float*)d_in[15];
    const float* ab2    = (const float*)d_in[16];

    float *q, *k, *v, *hid, *rpe, *vg, *attn, *part, *invn, *agg;
    int* nbr;
    cudaGetSymbolAddress((void**)&q,    g_q);
    cudaGetSymbolAddress((void**)&k,    g_k);
    cudaGetSymbolAddress((void**)&v,    g_v);
    cudaGetSymbolAddress((void**)&nbr,  g_nbr);
    cudaGetSymbolAddress((void**)&hid,  g_hid);
    cudaGetSymbolAddress((void**)&rpe,  g_rpe);
    cudaGetSymbolAddress((void**)&vg,   g_vg);
    cudaGetSymbolAddress((void**)&attn, g_attn);
    cudaGetSymbolAddress((void**)&part, g_part);
    cudaGetSymbolAddress((void**)&invn, g_invn);
    cudaGetSymbolAddress((void**)&agg,  g_agg);

    cudaFuncSetAttribute(mlp_kernel, cudaFuncAttributeMaxDynamicSharedMemorySize, SMEM_MLP_BYTES);

    // 1. KNN
    knn_kernel<<<BS*NPT, 256>>>(canon, nbr);
    // 2. fused QKV projections into (b,h,i,d) layout (one launch, 768 blocks)
    qkv_kernel<<<dim3(8, 32, 3), 256>>>(query, key_in, value, w_q, w_k, w_v, q, k, v);
    // 3. rpe
    hid_kernel<<<(BS*NPT*KNN*POSH + 255)/256, 256>>>(canon, nbr, pos_w1, pos_b1, hid);
    gemm64<<<dim3(8, 512), 256>>>(hid, pos_w2, pos_b2, rpe, 32768, 512, 64);
    // 4. fused gather + MLP + softmax (512 threads, 16 warps)
    mlp_kernel<<<dim3(64, 8, 2), 512, SMEM_MLP_BYTES>>>(q, k, v, rpe, nbr,
                                                        aw1, ab1, aw2, ab2, vg, attn);
    // 5. cross-i normalization
    norm_part_kernel<<<dim3(16, 8), 256>>>(attn, part);
    norm_final_kernel<<<16, 256>>>(part, invn);
    // 6. aggregate
    agg_kernel<<<dim3(256, 8, 2), 256>>>(attn, vg, invn, agg);
    // 7. output projection
    gemm64<<<dim3(8, 32), 256>>>(agg, w_out, b_out, (float*)d_out, 2048, 512, 512);
}

// round 10
// speedup vs baseline: 1.2675x; 1.2675x over previous
#include <cuda_runtime.h>
#include <cuda_bf16.h>
#include <math.h>

// Problem constants (fixed by setup_inputs)
#define BS 2
#define NPT 1024
#define HH 8
#define DH 64
#define KNN 16
#define EMB 512
#define INNER 512
#define AINNER 256
#define POSH 64

// ---------------- packed f32x2 helpers (sm_103a) ----------------
__device__ __forceinline__ unsigned long long pk2(float lo, float hi) {
    unsigned long long r;
    asm("mov.b64 %0, {%1, %2};" : "=l"(r) : "f"(lo), "f"(hi));
    return r;
}
__device__ __forceinline__ float2 upk2(unsigned long long p) {
    float lo, hi;
    asm("mov.b64 {%0, %1}, %2;" : "=f"(lo), "=f"(hi) : "l"(p));
    return make_float2(lo, hi);
}
#define FMA2(acc, a, b) \
    asm("fma.rn.f32x2 %0, %1, %2, %0;" : "+l"(acc) : "l"(a), "l"(b))

// ---------------- scratch (device globals; no allocation allowed) ----------------
__device__ float g_q[BS*HH*NPT*DH];     // (b,h,i,d)
__device__ float g_k[BS*HH*NPT*DH];
__device__ float g_v[BS*HH*NPT*DH];
__device__ int   g_nbr[BS*NPT*KNN];     // (b,i,j)
__device__ float g_hid[BS*NPT*KNN*POSH];
__device__ float g_rpe[BS*NPT*KNN*INNER];   // (b,i,j,hd)
__device__ float g_vg[BS*HH*NPT*KNN*DH];    // (b,h,i,j,d)
__device__ float g_attn[BS*HH*NPT*KNN*DH];  // (b,h,i,j,d)
__device__ float g_part[16*8*1024];
__device__ float g_invn[BS*HH*KNN*DH];      // (b,h,j,d)
__device__ float g_agg[BS*NPT*INNER];       // (b,i,hd)

// ---------------- KNN: per (b,i) top-16 smallest d2, tie-break lower idx ----------------
__global__ void knn_kernel(const float* __restrict__ canon, int* __restrict__ nbr) {
    int bi = blockIdx.x;               // 0..2047
    int b = bi >> 10, i = bi & 1023;
    __shared__ float dist[NPT];
    __shared__ unsigned long long red[8];
    const float* cb = canon + b * NPT * 3;
    float x = cb[i*3+0], y = cb[i*3+1], z = cb[i*3+2];
    for (int p = threadIdx.x; p < NPT; p += 256) {
        float dx = cb[p*3+0]-x, dy = cb[p*3+1]-y, dz = cb[p*3+2]-z;
        dist[p] = dx*dx + dy*dy + dz*dz;
    }
    __syncthreads();
    for (int s = 0; s < KNN; s++) {
        unsigned long long best = ~0ULL;
        for (int p = threadIdx.x; p < NPT; p += 256) {
            unsigned long long key = (((unsigned long long)__float_as_uint(dist[p])) << 32) | (unsigned)p;
            best = (key < best) ? key : best;
        }
        #pragma unroll
        for (int o = 16; o > 0; o >>= 1) {
            unsigned long long other = __shfl_xor_sync(0xffffffffu, best, o);
            best = (other < best) ? other : best;
        }
        if ((threadIdx.x & 31) == 0) red[threadIdx.x >> 5] = best;
        __syncthreads();
        if (threadIdx.x == 0) {
            unsigned long long m = red[0];
            #pragma unroll
            for (int w = 1; w < 8; w++) m = (red[w] < m) ? red[w] : m;
            int p = (int)(m & 0xffffffffu);
            nbr[bi*KNN + s] = p;
            dist[p] = __int_as_float(0x7f800000);  // +inf
        }
        __syncthreads();
    }
}

// ---------------- fused QKV projection: one launch, gridDim.z selects matrix ----------------
// C layout: scatter to (b,h,i,d); A: 2048x512, B: 512x512
__global__ __launch_bounds__(256) void qkv_kernel(
    const float* __restrict__ A0, const float* __restrict__ A1, const float* __restrict__ A2,
    const float* __restrict__ B0, const float* __restrict__ B1, const float* __restrict__ B2,
    float* __restrict__ C0, float* __restrict__ C1, float* __restrict__ C2)
{
    const int z = blockIdx.z;
    const float* A = (z == 0) ? A0 : (z == 1) ? A1 : A2;
    const float* B = (z == 0) ? B0 : (z == 1) ? B1 : B2;
    float*       C = (z == 0) ? C0 : (z == 1) ? C1 : C2;
    const int Kd = EMB, N = INNER;

    __shared__ float As[16][68];
    __shared__ float Bs[16][64];
    const int t = threadIdx.x;
    const int m0 = blockIdx.y * 64, n0 = blockIdx.x * 64;
    const int tx = t & 15, ty = t >> 4;
    const int am = t >> 2, ak = (t & 3) * 4;
    const int bk = t >> 4, bn = (t & 15) * 4;
    unsigned long long acc[4][2];
    #pragma unroll
    for (int u = 0; u < 4; u++) { acc[u][0] = 0ULL; acc[u][1] = 0ULL; }

    for (int k0 = 0; k0 < Kd; k0 += 16) {
        float4 av = *(const float4*)(A + (size_t)(m0 + am) * Kd + k0 + ak);
        float4 bv = *(const float4*)(B + (size_t)(bk + k0) * N + n0 + bn);
        As[ak+0][am] = av.x; As[ak+1][am] = av.y; As[ak+2][am] = av.z; As[ak+3][am] = av.w;
        *(float4*)&Bs[bk][bn] = bv;
        __syncthreads();
        #pragma unroll
        for (int k = 0; k < 16; k++) {
            float4 a = *(const float4*)&As[k][ty*4];
            float4 bq = *(const float4*)&Bs[k][tx*4];
            unsigned long long bp0 = pk2(bq.x, bq.y);
            unsigned long long bp1 = pk2(bq.z, bq.w);
            float ar[4] = {a.x, a.y, a.z, a.w};
            #pragma unroll
            for (int u = 0; u < 4; u++) {
                unsigned long long ap = pk2(ar[u], ar[u]);
                FMA2(acc[u][0], ap, bp0);
                FMA2(acc[u][1], ap, bp1);
            }
        }
        __syncthreads();
    }

    // scatter to (b,h,i,d) layout: row r=(b,i), col c=(h,d)
    int h = n0 >> 6;
    int d0 = tx * 4;
    #pragma unroll
    for (int u = 0; u < 4; u++) {
        int r = m0 + ty*4 + u;
        int b_ = r >> 10, i = r & 1023;
        float2 c0 = upk2(acc[u][0]), c1 = upk2(acc[u][1]);
        float4 o = make_float4(c0.x, c0.y, c1.x, c1.y);
        *(float4*)(C + ((size_t)((b_*8 + h)*1024 + i))*64 + d0) = o;
    }
}

// ---------------- generic 64x64-tile fp32 GEMM (packed f32x2 inner), C=A@B+bias ----------------
__global__ __launch_bounds__(256) void gemm64(
    const float* __restrict__ A, const float* __restrict__ B,
    const float* __restrict__ bias, float* __restrict__ C,
    int M, int N, int Kd)
{
    __shared__ float As[16][68];
    __shared__ float Bs[16][64];
    const int t = threadIdx.x;
    const int m0 = blockIdx.y * 64, n0 = blockIdx.x * 64;
    const int tx = t & 15, ty = t >> 4;
    const int am = t >> 2, ak = (t & 3) * 4;
    const int bk = t >> 4, bn = (t & 15) * 4;
    unsigned long long acc[4][2];
    #pragma unroll
    for (int u = 0; u < 4; u++) { acc[u][0] = 0ULL; acc[u][1] = 0ULL; }

    for (int k0 = 0; k0 < Kd; k0 += 16) {
        float4 av = *(const float4*)(A + (size_t)(m0 + am) * Kd + k0 + ak);
        float4 bv = *(const float4*)(B + (size_t)(bk + k0) * N + n0 + bn);
        As[ak+0][am] = av.x; As[ak+1][am] = av.y; As[ak+2][am] = av.z; As[ak+3][am] = av.w;
        *(float4*)&Bs[bk][bn] = bv;
        __syncthreads();
        #pragma unroll
        for (int k = 0; k < 16; k++) {
            float4 a = *(const float4*)&As[k][ty*4];
            float4 bq = *(const float4*)&Bs[k][tx*4];
            unsigned long long bp0 = pk2(bq.x, bq.y);
            unsigned long long bp1 = pk2(bq.z, bq.w);
            float ar[4] = {a.x, a.y, a.z, a.w};
            #pragma unroll
            for (int u = 0; u < 4; u++) {
                unsigned long long ap = pk2(ar[u], ar[u]);
                FMA2(acc[u][0], ap, bp0);
                FMA2(acc[u][1], ap, bp1);
            }
        }
        __syncthreads();
    }

    float4 bb = *(const float4*)(bias + n0 + tx*4);
    #pragma unroll
    for (int u = 0; u < 4; u++) {
        int m = m0 + ty*4 + u;
        float2 c0 = upk2(acc[u][0]), c1 = upk2(acc[u][1]);
        float4 o = make_float4(c0.x+bb.x, c0.y+bb.y, c1.x+bb.z, c1.y+bb.w);
        *(float4*)(C + (size_t)m * N + n0 + tx*4) = o;
    }
}

// ---------------- rpe hidden: relu(rel @ pos_w1 + pos_b1), per (b,i,j) ----------------
__global__ void hid_kernel(const float* __restrict__ canon, const int* __restrict__ nbr,
                           const float* __restrict__ w1, const float* __restrict__ b1,
                           float* __restrict__ hid)
{
    int idx = blockIdx.x * blockDim.x + threadIdx.x;   // over 32768*64
    if (idx >= BS*NPT*KNN*POSH) return;
    int row = idx >> 6, u = idx & 63;
    int b = row >> 14;              // row = b*16384 + i*16 + j
    int i = (row >> 4) & 1023;
    int nv = nbr[row];
    const float* cb = canon + b * NPT * 3;
    float r0 = cb[nv*3+0] - cb[i*3+0];
    float r1 = cb[nv*3+1] - cb[i*3+1];
    float r2 = cb[nv*3+2] - cb[i*3+2];
    float s = fmaf(r0, w1[0*64+u], fmaf(r1, w1[1*64+u], fmaf(r2, w1[2*64+u], b1[u])));
    hid[(size_t)row*64 + u] = fmaxf(s, 0.f);
}

// ---------------- rpe GEMM: C[32768,512] = hid[32768,64] @ w2[64,512] + b2 ----------------
// 64x128 tiles, K=64 single pass, float4 smem reads, FMA2. 51.2KB dyn smem -> 3 CTAs/SM.
#define RPE_AS_STRIDE 68
#define RPE_BS_STRIDE 132
#define RPE_SMEM_BYTES ((64*RPE_AS_STRIDE + 64*RPE_BS_STRIDE) * 4)

__global__ __launch_bounds__(256) void rpe_kernel(
    const float* __restrict__ A, const float* __restrict__ B,
    const float* __restrict__ bias, float* __restrict__ C)
{
    extern __shared__ float rsm[];
    float* As = rsm;                       // [k][m] stride 68
    float* Bs = rsm + 64*RPE_AS_STRIDE;    // [k][n] stride 132
    const int t = threadIdx.x;
    const int n0 = blockIdx.x * 128, m0 = blockIdx.y * 64;
    const int tx = t & 15, ty = t >> 4;

    // load A tile (64 rows x 64 k), transposed into As[k][m]
    {
        const int am = t >> 2;             // 0..63 row
        #pragma unroll
        for (int kk = 0; kk < 4; kk++) {
            int ak = (t & 3) * 4 + kk * 16;
            float4 av = *(const float4*)(A + (size_t)(m0 + am) * 64 + ak);
            As[(ak+0)*RPE_AS_STRIDE + am] = av.x;
            As[(ak+1)*RPE_AS_STRIDE + am] = av.y;
            As[(ak+2)*RPE_AS_STRIDE + am] = av.z;
            As[(ak+3)*RPE_AS_STRIDE + am] = av.w;
        }
    }
    // load B tile (64 k x 128 n)
    {
        const int bn = (t & 31) * 4;       // 0..124
        #pragma unroll
        for (int it = 0; it < 8; it++) {
            int bk = (t >> 5) + it * 8;    // 0..63
            float4 bv = *(const float4*)(B + (size_t)bk * INNER + n0 + bn);
            *(float4*)&Bs[bk*RPE_BS_STRIDE + bn] = bv;
        }
    }
    __syncthreads();

    unsigned long long acc[4][4];
    #pragma unroll
    for (int u = 0; u < 4; u++)
        #pragma unroll
        for (int vp = 0; vp < 4; vp++) acc[u][vp] = 0ULL;

    #pragma unroll 4
    for (int k = 0; k < 64; k++) {
        float4 a4 = *(const float4*)&As[k*RPE_AS_STRIDE + ty*4];
        float4 b0 = *(const float4*)&Bs[k*RPE_BS_STRIDE + tx*8];
        float4 b1 = *(const float4*)&Bs[k*RPE_BS_STRIDE + tx*8 + 4];
        unsigned long long bp[4] = {pk2(b0.x, b0.y), pk2(b0.z, b0.w),
                                    pk2(b1.x, b1.y), pk2(b1.z, b1.w)};
        float ar[4] = {a4.x, a4.y, a4.z, a4.w};
        #pragma unroll
        for (int u = 0; u < 4; u++) {
            unsigned long long ap = pk2(ar[u], ar[u]);
            #pragma unroll
            for (int vp = 0; vp < 4; vp++) FMA2(acc[u][vp], ap, bp[vp]);
        }
    }

    float4 bb0 = *(const float4*)(bias + n0 + tx*8);
    float4 bb1 = *(const float4*)(bias + n0 + tx*8 + 4);
    #pragma unroll
    for (int u = 0; u < 4; u++) {
        int m = m0 + ty*4 + u;
        float2 c0 = upk2(acc[u][0]), c1 = upk2(acc[u][1]);
        float2 c2 = upk2(acc[u][2]), c3 = upk2(acc[u][3]);
        float4 o0 = make_float4(c0.x+bb0.x, c0.y+bb0.y, c1.x+bb0.z, c1.y+bb0.w);
        float4 o1 = make_float4(c2.x+bb1.x, c2.y+bb1.y, c3.x+bb1.z, c3.y+bb1.w);
        *(float4*)(C + (size_t)m * INNER + n0 + tx*8)     = o0;
        *(float4*)(C + (size_t)m * INNER + n0 + tx*8 + 4) = o1;
    }
}

// ---------------- fused gather + attn MLP + softmax(j) (R4 scalar, 256 thr) ----------------
// block = (i-tile of 16) x (h) x (b); 256 threads; 256 rows = 16 i x 16 j
#define SMEM_XT   (64*257)
#define SMEM_HT   (64*260)
#define SMEM_W    (64*65)
#define SMEM_MLP_BYTES ((SMEM_XT + SMEM_HT + 2*SMEM_W) * 4)

__global__ __launch_bounds__(256, 1) void mlp_kernel(
    const float* __restrict__ qbuf, const float* __restrict__ kbuf, const float* __restrict__ vbuf,
    const float* __restrict__ rpe, const int* __restrict__ nbr,
    const float* __restrict__ aw1, const float* __restrict__ ab1,
    const float* __restrict__ aw2, const float* __restrict__ ab2,
    float* __restrict__ vg, float* __restrict__ attn)
{
    extern __shared__ float sm[];
    float* XT  = sm;                       // [d][r] stride 257
    float* HT  = sm + SMEM_XT;             // [e][r] stride 260 (reused as SIM [r][d] stride 65)
    float* W1s = sm + SMEM_XT + SMEM_HT;   // [d][e'] stride 65
    float* W2s = W1s + SMEM_W;             // [e'][d] stride 65
    const int t = threadIdx.x;
    const int it = blockIdx.x, h = blockIdx.y, b = blockIdx.z;
    const int i0 = it * 16;
    const int bh = b * 8 + h;

    // Phase 0: scrambled gather, build X = qg-kg+rpe (transposed in smem), write vg = vgath+rpe
    for (int idx = t; idx < 256 * 64; idx += 256) {
        const int r = idx >> 6, d = idx & 63;
        const int ii = r >> 4, j = r & 15;
        const int i = i0 + ii;
        const int nv = nbr[(b*1024 + h*128 + (i >> 3))*16 + ((i & 7)*2) + (j >> 3)];
        const int hs = nv >> 7;
        const int isrc = ((nv & 127) << 3) | (j & 7);
        const size_t src = ((size_t)((b*8 + hs)*1024 + isrc))*64 + d;
        const float rp = rpe[((size_t)((b*1024 + i)*16 + j))*512 + h*64 + d];
        XT[d*257 + r] = qbuf[src] - kbuf[src] + rp;
        vg[((size_t)((bh*1024 + i)*16 + j))*64 + d] = vbuf[src] + rp;
    }

    const int lane = t & 31, wg = t >> 5;
    float acc2[8][8];
    #pragma unroll
    for (int u = 0; u < 8; u++)
        #pragma unroll
        for (int v = 0; v < 8; v++) acc2[u][v] = 0.f;

    for (int ec = 0; ec < 4; ec++) {
        __syncthreads();
        // stage weights for this e-chunk
        for (int idx = t; idx < 4096; idx += 256) {
            int e = idx >> 6, d = idx & 63;
            W1s[d*65 + e] = aw1[(size_t)(h*256 + ec*64 + e)*64 + d];
        }
        for (int idx = t; idx < 4096; idx += 256) {
            int d = idx >> 6, e = idx & 63;
            W2s[e*65 + d] = aw2[(size_t)(h*64 + d)*256 + ec*64 + e];
        }
        __syncthreads();

        // GEMM1: H[r][e'] = relu(sum_d X[r][d]*aw1[e][d] + ab1[e])
        float acc1[8][8];
        #pragma unroll
        for (int u = 0; u < 8; u++)
            #pragma unroll
            for (int v = 0; v < 8; v++) acc1[u][v] = 0.f;
        #pragma unroll 4
        for (int d = 0; d < 64; d++) {
            float a[8], w[8];
            #pragma unroll
            for (int u = 0; u < 8; u++) a[u] = XT[d*257 + u*32 + lane];
            #pragma unroll
            for (int v = 0; v < 8; v++) w[v] = W1s[d*65 + wg*8 + v];
            #pragma unroll
            for (int u = 0; u < 8; u++)
                #pragma unroll
                for (int v = 0; v < 8; v++) acc1[u][v] = fmaf(a[u], w[v], acc1[u][v]);
        }
        #pragma unroll
        for (int v = 0; v < 8; v++) {
            float bb = ab1[h*256 + ec*64 + wg*8 + v];
            #pragma unroll
            for (int u = 0; u < 8; u++)
                HT[(wg*8 + v)*260 + u*32 + lane] = fmaxf(acc1[u][v] + bb, 0.f);
        }
        __syncthreads();

        // GEMM2: SIM[r][d] += sum_e' H[r][e']*aw2[d][e]
        #pragma unroll 4
        for (int e = 0; e < 64; e++) {
            float a[8], w[8];
            #pragma unroll
            for (int u = 0; u < 8; u++) a[u] = HT[e*260 + u*32 + lane];
            #pragma unroll
            for (int v = 0; v < 8; v++) w[v] = W2s[e*65 + wg*8 + v];
            #pragma unroll
            for (int u = 0; u < 8; u++)
                #pragma unroll
                for (int v = 0; v < 8; v++) acc2[u][v] = fmaf(a[u], w[v], acc2[u][v]);
        }
    }
    __syncthreads();

    // store SIM (+ab2) into smem (reuse HT space), stride 65
    float* SIM = HT;
    #pragma unroll
    for (int v = 0; v < 8; v++) {
        float bb = ab2[h*64 + wg*8 + v];
        #pragma unroll
        for (int u = 0; u < 8; u++)
            SIM[(u*32 + lane)*65 + wg*8 + v] = acc2[u][v] + bb;
    }
    __syncthreads();

    // softmax over j for each (ii, d)
    for (int p = t; p < 16 * 64; p += 256) {
        int ii = p >> 6, d = p & 63;
        int i = i0 + ii;
        float s[16];
        float m = -1e30f;
        #pragma unroll
        for (int j = 0; j < 16; j++) { s[j] = SIM[(ii*16 + j)*65 + d]; m = fmaxf(m, s[j]); }
        float sum = 0.f;
        #pragma unroll
        for (int j = 0; j < 16; j++) { s[j] = __expf(s[j] - m); sum += s[j]; }
        float inv = 1.f / sum;
        #pragma unroll
        for (int j = 0; j < 16; j++)
            attn[((size_t)((bh*1024 + i)*16 + j))*64 + d] = s[j] * inv;
    }
}

// ---------------- norm over i: partial sums then finalize 1/max(sqrt,1e-12) ----------------
__global__ void norm_part_kernel(const float* __restrict__ attn, float* __restrict__ part) {
    int bh = blockIdx.x, s = blockIdx.y;   // 16 x 8
    const float* base = attn + (size_t)bh * 1024 * 1024;
    float acc[4] = {0.f, 0.f, 0.f, 0.f};
    for (int i = s*128; i < s*128 + 128; i++) {
        #pragma unroll
        for (int q = 0; q < 4; q++) {
            int jd = q*256 + threadIdx.x;
            float v = base[(size_t)i*1024 + jd];
            acc[q] = fmaf(v, v, acc[q]);
        }
    }
    #pragma unroll
    for (int q = 0; q < 4; q++)
        part[(size_t)(bh*8 + s)*1024 + q*256 + threadIdx.x] = acc[q];
}

__global__ void norm_final_kernel(const float* __restrict__ part, float* __restrict__ invn) {
    int bh = blockIdx.x;
    #pragma unroll
    for (int q = 0; q < 4; q++) {
        int jd = q*256 + threadIdx.x;
        float s = 0.f;
        #pragma unroll
        for (int seg = 0; seg < 8; seg++) s += part[(size_t)(bh*8 + seg)*1024 + jd];
        float n = sqrtf(s);
        invn[bh*1024 + jd] = 1.f / fmaxf(n, 1e-12f);
    }
}

// ---------------- aggregate: agg[b,i,h*64+d] = sum_j attn*inv_norm*vg ----------------
__global__ void agg_kernel(const float* __restrict__ attn, const float* __restrict__ vg,
                           const float* __restrict__ invn, float* __restrict__ aggb) {
    int ic = blockIdx.x, h = blockIdx.y, b = blockIdx.z;   // 256 x 8 x 2
    int bh = b*8 + h;
    __shared__ float inv_s[1024];
    for (int p = threadIdx.x; p < 1024; p += 256) inv_s[p] = invn[bh*1024 + p];
    __syncthreads();
    int ii = threadIdx.x >> 6, d = threadIdx.x & 63;
    int i = ic*4 + ii;
    const float* ab = attn + (size_t)(bh*1024 + i) * 1024;
    const float* vb = vg + (size_t)(bh*1024 + i) * 1024;
    float acc = 0.f;
    #pragma unroll
    for (int j = 0; j < 16; j++)
        acc = fmaf(ab[j*64 + d] * inv_s[j*64 + d], vb[j*64 + d], acc);
    aggb[(size_t)(b*1024 + i)*512 + h*64 + d] = acc;
}

// ---------------- host launcher ----------------
extern "C" void kernel_launch(void* const* d_in, const int* in_sizes, int n_in,
                              void* d_out, int out_size) {
    const float* query  = (const float*)d_in[0];
    const float* key_in = (const float*)d_in[1];
    const float* value  = (const float*)d_in[2];
    const float* canon  = (const float*)d_in[3];
    const float* w_q    = (const float*)d_in[4];
    const float* w_k    = (const float*)d_in[5];
    const float* w_v    = (const float*)d_in[6];
    const float* w_out  = (const float*)d_in[7];
    const float* b_out  = (const float*)d_in[8];
    const float* pos_w1 = (const float*)d_in[9];
    const float* pos_b1 = (const float*)d_in[10];
    const float* pos_w2 = (const float*)d_in[11];
    const float* pos_b2 = (const float*)d_in[12];
    const float* aw1    = (const float*)d_in[13];
    const float* ab1    = (const float*)d_in[14];
    const float* aw2    = (const float*)d_in[15];
    const float* ab2    = (const float*)d_in[16];

    float *q, *k, *v, *hid, *rpe, *vg, *attn, *part, *invn, *agg;
    int* nbr;
    cudaGetSymbolAddress((void**)&q,    g_q);
    cudaGetSymbolAddress((void**)&k,    g_k);
    cudaGetSymbolAddress((void**)&v,    g_v);
    cudaGetSymbolAddress((void**)&nbr,  g_nbr);
    cudaGetSymbolAddress((void**)&hid,  g_hid);
    cudaGetSymbolAddress((void**)&rpe,  g_rpe);
    cudaGetSymbolAddress((void**)&vg,   g_vg);
    cudaGetSymbolAddress((void**)&attn, g_attn);
    cudaGetSymbolAddress((void**)&part, g_part);
    cudaGetSymbolAddress((void**)&invn, g_invn);
    cudaGetSymbolAddress((void**)&agg,  g_agg);

    cudaFuncSetAttribute(mlp_kernel, cudaFuncAttributeMaxDynamicSharedMemorySize, SMEM_MLP_BYTES);
    cudaFuncSetAttribute(rpe_kernel, cudaFuncAttributeMaxDynamicSharedMemorySize, RPE_SMEM_BYTES);

    // 1. KNN
    knn_kernel<<<BS*NPT, 256>>>(canon, nbr);
    // 2. fused QKV projections into (b,h,i,d) layout (one launch, 768 blocks)
    qkv_kernel<<<dim3(8, 32, 3), 256>>>(query, key_in, value, w_q, w_k, w_v, q, k, v);
    // 3. rpe
    hid_kernel<<<(BS*NPT*KNN*POSH + 255)/256, 256>>>(canon, nbr, pos_w1, pos_b1, hid);
    rpe_kernel<<<dim3(4, 512), 256, RPE_SMEM_BYTES>>>(hid, pos_w2, pos_b2, rpe);
    // 4. fused gather + MLP + softmax (R4 scalar, 256 threads)
    mlp_kernel<<<dim3(64, 8, 2), 256, SMEM_MLP_BYTES>>>(q, k, v, rpe, nbr,
                                                        aw1, ab1, aw2, ab2, vg, attn);
    // 5. cross-i normalization
    norm_part_kernel<<<dim3(16, 8), 256>>>(attn, part);
    norm_final_kernel<<<16, 256>>>(part, invn);
    // 6. aggregate
    agg_kernel<<<dim3(256, 8, 2), 256>>>(attn, vg, invn, agg);
    // 7. output projection
    gemm64<<<dim3(8, 32), 256>>>(agg, w_out, b_out, (float*)d_out, 2048, 512, 512);
}